// round 12
// baseline (speedup 1.0000x reference)
#include <cuda_runtime.h>

#define HD      768
#define SEQ     256
#define BATCH   4
#define ROWS    1024
#define NP      54
#define THRESH  0.5f
#define ROWOUT  (SEQ * NP)          // 13824
#define CROWS   (ROWS * HD)         // 786432 floats per split buffer

typedef unsigned long long u64;

// Scratch (device globals — no allocation allowed)
__device__ float g_c[3 * CROWS];          // split-K partials of x @ W1s^T
__device__ float g_habC[ROWS * 2 * HD];   // COMPACT: [slot][ha(768) | hb(768)]
__device__ int   g_cand[ROWS];
__device__ int   g_rows[ROWS];            // slot -> row
__device__ int   g_slot[ROWS];            // row -> slot (valid if cand)
__device__ int   g_pairs[BATCH * SEQ * SEQ];
__device__ int   g_cnt;
__device__ int   g_nrows;

__device__ __forceinline__ void fma2(u64& d, u64 a, u64 b) {
    asm("fma.rn.f32x2 %0, %1, %2, %0;" : "+l"(d) : "l"(a), "l"(b));
}
__device__ __forceinline__ u64 dup2(float a) {
    u64 r; asm("mov.b64 %0, {%1, %1};" : "=l"(r) : "f"(a)); return r;
}
__device__ __forceinline__ void unpack2(float& lo, float& hi, u64 v) {
    asm("mov.b64 {%0, %1}, %2;" : "=f"(lo), "=f"(hi) : "l"(v));
}

// ---------------------------------------------------------------------------
// GEMM: partial c = x[:, ks:ks+256] @ W1s[:, ks:ks+256]^T  -> g_c[split]
// BM=128, BN=64, BK=16, 256 threads, m-pair packed FFMA2, split-K = 3.
// Trickles the 56.6MB output zero-fill through the k-loop.
// ---------------------------------------------------------------------------
#define BM 128
#define BN 64
#define BK 16
#define KSPLIT 256
#define LDA 132
#define LDB 68

__global__ void __launch_bounds__(256, 2) gemm_kernel(
    const float* __restrict__ X,
    const float* __restrict__ W1s,
    float* __restrict__ out)
{
    __shared__ float As[2][BK * LDA];
    __shared__ float Bs[2][BK * LDB];

    const int tid = threadIdx.x;
    const int n0 = blockIdx.x * BN;
    const int m0 = blockIdx.y * BM;
    const int ks = blockIdx.z * KSPLIT;
    const int ty = tid >> 4;
    const int tx = tid & 15;

    const int ctaid = blockIdx.z * 96 + blockIdx.y * 12 + blockIdx.x;  // 0..287
    if (ctaid == 0 && tid == 0) { g_nrows = 0; g_cnt = 0; }
    float4* o4 = (float4*)out + ctaid * 12288 + tid;

    const int am  = tid >> 2;
    const int akq = (tid & 3) * 4;
    const int bn  = tid & 63;
    const int bkq = (tid >> 6) * 4;

    const float* gA0 = X + (m0 + am) * HD + ks + akq;
    const float* gA1 = gA0 + 64 * HD;
    const float* gB  = W1s + (n0 + bn) * HD + ks + bkq;

    u64 acc[4][4];
    #pragma unroll
    for (int j = 0; j < 4; j++)
        #pragma unroll
        for (int ip = 0; ip < 4; ip++) acc[j][ip] = 0ull;

    float4 ra0, ra1, rb;

    ra0 = *(const float4*)gA0;
    ra1 = *(const float4*)gA1;
    rb  = *(const float4*)gB;
    {
        As[0][(akq+0)*LDA + am]      = ra0.x;  As[0][(akq+1)*LDA + am]      = ra0.y;
        As[0][(akq+2)*LDA + am]      = ra0.z;  As[0][(akq+3)*LDA + am]      = ra0.w;
        As[0][(akq+0)*LDA + am + 64] = ra1.x;  As[0][(akq+1)*LDA + am + 64] = ra1.y;
        As[0][(akq+2)*LDA + am + 64] = ra1.z;  As[0][(akq+3)*LDA + am + 64] = ra1.w;
        Bs[0][(bkq+0)*LDB + bn] = rb.x;  Bs[0][(bkq+1)*LDB + bn] = rb.y;
        Bs[0][(bkq+2)*LDB + bn] = rb.z;  Bs[0][(bkq+3)*LDB + bn] = rb.w;
    }
    ra0 = *(const float4*)(gA0 + BK);
    ra1 = *(const float4*)(gA1 + BK);
    rb  = *(const float4*)(gB  + BK);

    const int NITER = KSPLIT / BK;   // 16
    const float4 z4 = make_float4(0.f, 0.f, 0.f, 0.f);

    for (int it = 0; it < NITER; it++) {
        __syncthreads();
        const int cb = it & 1;

        o4[(it * 3 + 0) * 256] = z4;
        o4[(it * 3 + 1) * 256] = z4;
        o4[(it * 3 + 2) * 256] = z4;

        #pragma unroll
        for (int k = 0; k < BK; k++) {
            ulonglong2 a01 = *(const ulonglong2*)&As[cb][k * LDA + ty * 8];
            ulonglong2 a23 = *(const ulonglong2*)&As[cb][k * LDA + ty * 8 + 4];
            float4 bf = *(const float4*)&Bs[cb][k * LDB + tx * 4];
            u64 ap[4] = {a01.x, a01.y, a23.x, a23.y};
            u64 bd[4] = {dup2(bf.x), dup2(bf.y), dup2(bf.z), dup2(bf.w)};
            #pragma unroll
            for (int j = 0; j < 4; j++)
                #pragma unroll
                for (int ip = 0; ip < 4; ip++)
                    fma2(acc[j][ip], ap[ip], bd[j]);
        }

        if (it + 1 < NITER) {
            const int sb = (it + 1) & 1;
            As[sb][(akq+0)*LDA + am]      = ra0.x;  As[sb][(akq+1)*LDA + am]      = ra0.y;
            As[sb][(akq+2)*LDA + am]      = ra0.z;  As[sb][(akq+3)*LDA + am]      = ra0.w;
            As[sb][(akq+0)*LDA + am + 64] = ra1.x;  As[sb][(akq+1)*LDA + am + 64] = ra1.y;
            As[sb][(akq+2)*LDA + am + 64] = ra1.z;  As[sb][(akq+3)*LDA + am + 64] = ra1.w;
            Bs[sb][(bkq+0)*LDB + bn] = rb.x;  Bs[sb][(bkq+1)*LDB + bn] = rb.y;
            Bs[sb][(bkq+2)*LDB + bn] = rb.z;  Bs[sb][(bkq+3)*LDB + bn] = rb.w;
            if (it + 2 < NITER) {
                int ko = (it + 2) * BK;
                ra0 = *(const float4*)(gA0 + ko);
                ra1 = *(const float4*)(gA1 + ko);
                rb  = *(const float4*)(gB  + ko);
            }
        }
    }

    float cv[8][4];
    #pragma unroll
    for (int j = 0; j < 4; j++)
        #pragma unroll
        for (int ip = 0; ip < 4; ip++)
            unpack2(cv[2*ip][j], cv[2*ip+1][j], acc[j][ip]);

    float* cb = g_c + blockIdx.z * CROWS;
    #pragma unroll
    for (int i = 0; i < 8; i++) {
        int m = m0 + ty * 8 + i;
        *(float4*)&cb[m * HD + n0 + tx * 4] =
            make_float4(cv[i][0], cv[i][1], cv[i][2], cv[i][3]);
    }
}

// ---------------------------------------------------------------------------
// CAND: warp per row; builds row list + inverse slot map.
// ---------------------------------------------------------------------------
__global__ void __launch_bounds__(256) cand_kernel(
    const float* __restrict__ b1s,
    const float* __restrict__ W2s,
    const float* __restrict__ b2s)
{
    const int row  = (blockIdx.x * 256 + threadIdx.x) >> 5;
    const int lane = threadIdx.x & 31;
    float s = 0.f;
    #pragma unroll
    for (int t = 0; t < HD / 32; t++) {
        int k = lane + 32 * t;
        float c = g_c[row * HD + k] + g_c[CROWS + row * HD + k]
                + g_c[2 * CROWS + row * HD + k];
        s += fmaxf(c + b1s[k], 0.f) * W2s[k];
    }
    #pragma unroll
    for (int o = 16; o > 0; o >>= 1)
        s += __shfl_xor_sync(0xffffffffu, s, o);
    if (lane == 0) {
        int c = (s + b2s[0]) > THRESH ? 1 : 0;
        g_cand[row] = c;
        if (c) {
            int r = atomicAdd(&g_nrows, 1);
            g_rows[r] = row;
            g_slot[row] = r;
        }
    }
}

// ---------------------------------------------------------------------------
// COMPACT: single block; builds explicit pair list (segment-reserved).
// ---------------------------------------------------------------------------
__global__ void __launch_bounds__(256) compact_kernel()
{
    __shared__ int fc[ROWS];
    const int t = threadIdx.x;
    for (int r = t; r < ROWS; r += 256) fc[r] = g_cand[r];
    __syncthreads();
    for (int r = t; r < ROWS; r += 256) {
        if (!fc[r]) continue;
        const int b0 = r & ~255;
        const int i  = r & 255;
        int cnt = 0;
        for (int j = 0; j < SEQ; j++)
            if (fc[b0 + j] && j != i) cnt++;
        if (cnt) {
            int p = atomicAdd(&g_cnt, cnt);
            for (int j = 0; j < SEQ; j++)
                if (fc[b0 + j] && j != i)
                    g_pairs[p++] = r * SEQ + j;       // rowi*256 + j
        }
    }
}

// ---------------------------------------------------------------------------
// HAB: one WARP per (candidate slot, column); float4 loads; COMPACT output.
// ---------------------------------------------------------------------------
__global__ void __launch_bounds__(256) hab_kernel(
    const float* __restrict__ X,
    const float* __restrict__ Wp1)
{
    const int lane   = threadIdx.x & 31;
    const int gwarp  = (blockIdx.x * 256 + threadIdx.x) >> 5;
    const int nwarps = gridDim.x * 8;
    const int total  = g_nrows * 1536;

    for (int item = gwarp; item < total; item += nwarps) {
        const int rs  = item / 1536;
        const int c   = item - rs * 1536;
        const int row = g_rows[rs];
        const float4* xr = (const float4*)(X + row * HD);
        const float* wr  = (c < HD) ? (Wp1 + (size_t)c * (2 * HD))
                                    : (Wp1 + (size_t)(c - HD) * (2 * HD) + HD);
        const float4* w4 = (const float4*)wr;
        float s = 0.f;
        #pragma unroll
        for (int t = 0; t < HD / 128; t++) {
            int k = lane + 32 * t;
            float4 xv = __ldg(&xr[k]);
            float4 wv = __ldg(&w4[k]);
            s += xv.x * wv.x + xv.y * wv.y + xv.z * wv.z + xv.w * wv.w;
        }
        #pragma unroll
        for (int o = 16; o > 0; o >>= 1)
            s += __shfl_xor_sync(0xffffffffu, s, o);
        if (lane == 0) g_habC[(size_t)rs * (2 * HD) + c] = s;
    }
}

// ---------------------------------------------------------------------------
// PAIR: list-driven, one block per pair (grid-stride over g_cnt).
// Reads COMPACT habC (L2-hot). 7-accumulator ILP dots per warp.
// ---------------------------------------------------------------------------
__global__ void __launch_bounds__(256) pair_kernel(
    const float* __restrict__ bp1,
    const float* __restrict__ Wp2,
    const float* __restrict__ bp2,
    float* __restrict__ out)
{
    __shared__ float v[HD];
    const int tid  = threadIdx.x;
    const int warp = tid >> 5;
    const int lane = tid & 31;
    const int cnt  = g_cnt;

    for (int p = blockIdx.x; p < cnt; p += gridDim.x) {
        const int code = g_pairs[p];
        const int rowi = code >> 8;
        const int j    = code & 255;
        const int rowj = (rowi & ~255) | j;
        const int si   = g_slot[rowi];
        const int sj   = g_slot[rowj];

        __syncthreads();
        for (int k = tid; k < HD; k += 256)
            v[k] = fmaxf(g_habC[(size_t)si * (2 * HD) + k] +
                         g_habC[(size_t)sj * (2 * HD) + HD + k] + bp1[k], 0.f);
        __syncthreads();

        // warp w -> logits 7w .. 7w+6
        const int p0 = warp * 7;
        float acc[7];
        #pragma unroll
        for (int q = 0; q < 7; q++) acc[q] = 0.f;

        #pragma unroll
        for (int t = 0; t < HD / 32; t++) {
            int k = lane + 32 * t;
            float vv = v[k];
            #pragma unroll
            for (int q = 0; q < 7; q++) {
                int pp = p0 + q;
                if (pp < NP)
                    acc[q] += vv * __ldg(&Wp2[pp * HD + k]);
            }
        }
        #pragma unroll
        for (int q = 0; q < 7; q++) {
            #pragma unroll
            for (int off = 16; off > 0; off >>= 1)
                acc[q] += __shfl_xor_sync(0xffffffffu, acc[q], off);
        }
        if (lane == 0) {
            float* o = out + (size_t)code * NP;   // code == rowi*SEQ + j
            #pragma unroll
            for (int q = 0; q < 7; q++) {
                int pp = p0 + q;
                if (pp < NP) o[pp] = acc[q] + bp2[pp];
            }
        }
    }
}

// ---------------------------------------------------------------------------
extern "C" void kernel_launch(void* const* d_in, const int* in_sizes, int n_in,
                              void* d_out, int out_size)
{
    const float* x   = (const float*)d_in[0];
    const float* W1s = (const float*)d_in[1];
    const float* b1s = (const float*)d_in[2];
    const float* W2s = (const float*)d_in[3];
    const float* b2s = (const float*)d_in[4];
    const float* Wp1 = (const float*)d_in[5];
    const float* bp1 = (const float*)d_in[6];
    const float* Wp2 = (const float*)d_in[7];
    const float* bp2 = (const float*)d_in[8];
    float* out = (float*)d_out;

    // 1) split-K partial GEMM + fused output zero-fill + counter resets
    dim3 g1(HD / BN, ROWS / BM, 3);              // 288 CTAs, single wave
    gemm_kernel<<<g1, 256>>>(x, W1s, out);

    // 2) candidate mask + row list + slot map
    cand_kernel<<<ROWS / 8, 256>>>(b1s, W2s, b2s);

    // 3) explicit pair list (single small block)
    compact_kernel<<<1, 256>>>();

    // 4) ha/hb -> compact slot-indexed buffer
    hab_kernel<<<512, 256>>>(x, Wp1);

    // 5) pair logits, list-driven
    pair_kernel<<<512, 256>>>(bp1, Wp2, bp2, out);
}